// round 13
// baseline (speedup 1.0000x reference)
#include <cuda_runtime.h>
#include <cuda_fp16.h>
#include <math.h>
#include <stdint.h>

#define N 8192
#define D 32
#define NB 64
#define B 128
#define GAMMA 0.03125f
#define REG 1e-3f
#define GRID_CHOL 148
#define NTHR 512
#define SP 272u              // smem row pitch (bytes) for fp16 operand tiles
#define A0_OFF 0u
#define A1_OFF 69632u        // 256*272
#define B0_OFF 139264u       // 2*256*272
#define B1_OFF 174080u       // +128*272
#define CHOL_DYN 208896u     // B1_OFF + 128*272

// ---------------- device scratch ----------------
__device__ float g_A[(size_t)N * N];
__device__ float g_invL[(size_t)NB * B * B];
__device__ __align__(16) __half g_L0[(size_t)N * N];
__device__ __align__(16) __half g_L1[(size_t)N * N];
__device__ __align__(16) __half g_W0[(size_t)NB * B * B];
__device__ __align__(16) __half g_W1[(size_t)NB * B * B];
__device__ float g_xx[N];
__device__ float g_r[N];
__device__ float g_zsol[N];
__device__ float g_alpha[N];
// accumulating sync state (epoch-based; never reset)
__device__ int g_tflag[NB * NB];   // [k*NB+i] trsm tile (i,k) done
__device__ int g_ucnt[NB * NB];    // [a*NB+b] update count of C tile
__device__ int g_dflag[NB];        // potf(k) done
__device__ int g_next;
__device__ int g_ecnt;
__device__ int g_ff[NB];
__device__ int g_fb[NB];
__device__ int g_fep;
__device__ int g_bep;

// ---------------- helpers ----------------
__device__ __forceinline__ uint32_t s2u(const void* p) {
    uint32_t a;
    asm("{ .reg .u64 t; cvta.to.shared.u64 t, %1; cvt.u32.u64 %0, t; }" : "=r"(a) : "l"(p));
    return a;
}
__device__ __forceinline__ void ldsm_x4(uint32_t* d, uint32_t addr) {
    asm volatile("ldmatrix.sync.aligned.m8n8.x4.shared.b16 {%0,%1,%2,%3}, [%4];"
        : "=r"(d[0]), "=r"(d[1]), "=r"(d[2]), "=r"(d[3]) : "r"(addr));
}
__device__ __forceinline__ void ldsm_x2(uint32_t* d, uint32_t addr) {
    asm volatile("ldmatrix.sync.aligned.m8n8.x2.shared.b16 {%0,%1}, [%2];"
        : "=r"(d[0]), "=r"(d[1]) : "r"(addr));
}
__device__ __forceinline__ void mma16816(float* c, const uint32_t* a, const uint32_t* b) {
    asm volatile("mma.sync.aligned.m16n8k16.row.col.f32.f16.f16.f32 "
        "{%0,%1,%2,%3}, {%4,%5,%6,%7}, {%8,%9}, {%0,%1,%2,%3};"
        : "+f"(c[0]), "+f"(c[1]), "+f"(c[2]), "+f"(c[3])
        : "r"(a[0]), "r"(a[1]), "r"(a[2]), "r"(a[3]), "r"(b[0]), "r"(b[1]));
}
__device__ __forceinline__ void cpasync16(uint32_t saddr, const void* g) {
    asm volatile("cp.async.cg.shared.global [%0], [%1], 16;" :: "r"(saddr), "l"(g));
}
__device__ __forceinline__ void split2(float x, __half& h0, __half& h1) {
    h0 = __float2half_rn(x);
    h1 = __float2half_rn(x - __half2float(h0));
}
__device__ __forceinline__ void tri_decode_row(int p, int& ti, int& tj) {
    float pf = sqrtf(8.f * (float)p + 1.f);
    int i = (int)((pf - 1.f) * 0.5f);
    while ((i + 1) * (i + 2) / 2 <= p) i++;
    while (i * (i + 1) / 2 > p) i--;
    ti = i; tj = p - i * (i + 1) / 2;
}
// per-column supertask counts
__device__ __forceinline__ void col_counts(int k, int& SR, int& S) {
    int nb = NB - 1 - k;
    SR = (nb + 1) >> 1;
    int m = nb >> 1;
    S = (nb & 1) ? (m * m + 3 * m + 1) : (m * (m + 1));
}

__global__ void noop_kernel() {}

// ---------------- prep ----------------
__global__ void prep_kernel(const float* __restrict__ Xtr, const float* __restrict__ y) {
    int i = blockIdx.x * 256 + threadIdx.x;
    float s = 0.f;
#pragma unroll
    for (int dg = 0; dg < 8; dg++) {
        float4 v = *(const float4*)(Xtr + (size_t)i * D + dg * 4);
        s += v.x * v.x + v.y * v.y + v.z * v.z + v.w * v.w;
    }
    g_xx[i] = s;
    g_r[i] = y[i];
}

// ---------------- build gram (lower triangle of 128-blocks) ----------------
__global__ void __launch_bounds__(256, 2) build_kernel(const float* __restrict__ Xtr) {
    __shared__ float sXi[32 * 132];
    __shared__ float sXj[32 * 132];
    __shared__ float sxxi[128], sxxj[128];
    int tid = threadIdx.x;
    int bi, bj;
    tri_decode_row(blockIdx.x, bi, bj);

#pragma unroll
    for (int i = 0; i < 4; i++) {
        int f = tid + i * 256;
        int r = f >> 3;
        int dg = (f & 7) << 2;
        float4 v = *(const float4*)(Xtr + (size_t)(bi * B + r) * D + dg);
        sXi[(dg + 0) * 132 + r] = v.x; sXi[(dg + 1) * 132 + r] = v.y;
        sXi[(dg + 2) * 132 + r] = v.z; sXi[(dg + 3) * 132 + r] = v.w;
        float4 w = *(const float4*)(Xtr + (size_t)(bj * B + r) * D + dg);
        sXj[(dg + 0) * 132 + r] = w.x; sXj[(dg + 1) * 132 + r] = w.y;
        sXj[(dg + 2) * 132 + r] = w.z; sXj[(dg + 3) * 132 + r] = w.w;
    }
    if (tid < 128) { sxxi[tid] = g_xx[bi * B + tid]; sxxj[tid] = g_xx[bj * B + tid]; }
    __syncthreads();

    int tm = tid >> 4, tn = tid & 15;
    float acc[8][8];
#pragma unroll
    for (int i = 0; i < 8; i++)
#pragma unroll
        for (int j = 0; j < 8; j++) acc[i][j] = 0.f;

#pragma unroll
    for (int d = 0; d < 32; d++) {
        float a[8], b[8];
        *(float4*)(a)     = *(const float4*)(&sXi[d * 132 + tm * 8]);
        *(float4*)(a + 4) = *(const float4*)(&sXi[d * 132 + tm * 8 + 4]);
        *(float4*)(b)     = *(const float4*)(&sXj[d * 132 + tn * 8]);
        *(float4*)(b + 4) = *(const float4*)(&sXj[d * 132 + tn * 8 + 4]);
#pragma unroll
        for (int i = 0; i < 8; i++)
#pragma unroll
            for (int j = 0; j < 8; j++) acc[i][j] += a[i] * b[j];
    }

#pragma unroll
    for (int i = 0; i < 8; i++) {
        int li = tm * 8 + i;
        int gi = bi * B + li;
        float v[8];
#pragma unroll
        for (int j = 0; j < 8; j++) {
            int lj = tn * 8 + j;
            int gj = bj * B + lj;
            float sq = sxxi[li] + sxxj[lj] - 2.f * acc[i][j];
            sq = fmaxf(sq, 0.f);
            float val = __expf(-GAMMA * sq);
            if (gi == gj) val += REG;
            v[j] = val;
        }
        float* cp = g_A + (size_t)gi * N + bj * B + tn * 8;
        *(float4*)(cp)     = make_float4(v[0], v[1], v[2], v[3]);
        *(float4*)(cp + 4) = make_float4(v[4], v[5], v[6], v[7]);
    }
}

// ---------------- staging ----------------
// A supertile: 256 rows (dup via rmask) x 128 cols fp16, 2 splits, ld = N
__device__ __forceinline__ void stage_A(const __half* p0, const __half* p1,
                                        int rmask, uint32_t sbase, int tid) {
#pragma unroll
    for (int i = 0; i < 16; i++) {
        int f = tid + (i << 9);
        int s = f >> 12;
        int rem = f & 4095;
        int r = rem >> 4;
        int seg = rem & 15;
        const __half* p = s ? p1 : p0;
        cpasync16(sbase + (s ? A1_OFF : A0_OFF) + (uint32_t)r * SP + seg * 16,
                  p + (size_t)(r & rmask) * N + seg * 8);
    }
}
// B tile: 128 rows x 128 cols fp16, 2 splits, arbitrary ld
__device__ __forceinline__ void stage_B(const __half* p0, const __half* p1,
                                        int ld, uint32_t sbase, int tid) {
#pragma unroll
    for (int i = 0; i < 8; i++) {
        int f = tid + (i << 9);
        int s = f >> 11;
        int rem = f & 2047;
        int r = rem >> 4;
        int seg = rem & 15;
        const __half* p = s ? p1 : p0;
        cpasync16(sbase + (s ? B1_OFF : B0_OFF) + (uint32_t)r * SP + seg * 16,
                  p + (size_t)r * ld + seg * 8);
    }
}

// ---------------- compute: full-K 256x128 supertile, fp16x2 (3 products) ----------------
__device__ __forceinline__ void compute_tile(uint32_t sbase, int lane, int wm, int wn,
                                             float acc[4][4][4]) {
#pragma unroll
    for (int kt = 0; kt < 8; kt++) {
#pragma unroll
        for (int sa = 0; sa < 2; sa++) {
            uint32_t af[4][4];
#pragma unroll
            for (int mt = 0; mt < 4; mt++) {
                int rrow = wm * 64 + mt * 16 + (lane & 15);
                int col = kt * 16 + (lane >> 4) * 8;
                ldsm_x4(af[mt], sbase + (sa ? A1_OFF : A0_OFF) + (uint32_t)rrow * SP + col * 2);
            }
#pragma unroll
            for (int sb = 0; sb < 2; sb++) {
                if (sa + sb > 1) continue;
                uint32_t bfr[4][2];
#pragma unroll
                for (int nt = 0; nt < 4; nt++) {
                    int n = wn * 32 + nt * 8 + (lane & 7);
                    int col = kt * 16 + ((lane >> 3) & 1) * 8;
                    ldsm_x2(bfr[nt], sbase + (sb ? B1_OFF : B0_OFF) + (uint32_t)n * SP + col * 2);
                }
#pragma unroll
                for (int mt = 0; mt < 4; mt++)
#pragma unroll
                    for (int nt = 0; nt < 4; nt++)
                        mma16816(acc[mt][nt], af[mt], bfr[nt]);
            }
        }
    }
}

// ---------------- potf: factor diag block kb, write invL + fp16 splits (512 thr) ----------------
__device__ void potf_block(int kb, float* sD, float* invd, float* rowbuf) {
    int tid = threadIdx.x;
    size_t base = (size_t)(kb * B) * N + (size_t)kb * B;

    for (int idx = tid; idx < B * B; idx += NTHR) {
        int r = idx >> 7, c = idx & 127;
        sD[r * 129 + c] = g_A[base + (size_t)r * N + c];
    }
    __syncthreads();

    int tr = tid & 31, tj2 = tid >> 5;
    for (int c = 0; c < B - 1; c++) {
        float ipiv = __fdividef(1.f, sD[c * 129 + c]);
        for (int r = c + 1 + tr; r < B; r += 32) {
            float a = sD[r * 129 + c] * ipiv;
            for (int jj = c + 1 + tj2; jj <= r; jj += 16)
                sD[r * 129 + jj] -= a * sD[jj * 129 + c];
        }
        __syncthreads();
    }
    for (int c = tid; c < B; c += NTHR) invd[c] = rsqrtf(sD[c * 129 + c]);
    __syncthreads();
    for (int idx = tid; idx < B * B; idx += NTHR) {
        int r = idx >> 7, c = idx & 127;
        if (c < r) sD[r * 129 + c] *= invd[c];
        else if (c == r) sD[r * 129 + c] = invd[c];
    }
    __syncthreads();

    for (int r = 1; r < B; r++) {
        for (int c = tid; c < r; c += NTHR) rowbuf[c] = sD[r * 129 + c];
        __syncthreads();
        if (tid < r) {
            int c = tid;
            float a0 = 0.f, a1 = 0.f, a2 = 0.f, a3 = 0.f;
            int jj = c;
            for (; jj + 3 < r; jj += 4) {
                a0 += rowbuf[jj]     * sD[jj * 129 + c];
                a1 += rowbuf[jj + 1] * sD[(jj + 1) * 129 + c];
                a2 += rowbuf[jj + 2] * sD[(jj + 2) * 129 + c];
                a3 += rowbuf[jj + 3] * sD[(jj + 3) * 129 + c];
            }
            for (; jj < r; jj++) a0 += rowbuf[jj] * sD[jj * 129 + c];
            sD[r * 129 + c] = -invd[r] * ((a0 + a1) + (a2 + a3));
        }
        __syncthreads();
    }
    size_t koff = (size_t)kb * B * B;
    for (int idx = tid; idx < B * B; idx += NTHR) {
        int r = idx >> 7, c = idx & 127;
        float w = (c <= r) ? sD[r * 129 + c] : 0.f;
        g_invL[koff + idx] = w;
        __half h0, h1;
        split2(w, h0, h1);
        g_W0[koff + idx] = h0;
        g_W1[koff + idx] = h1;
    }
    __syncthreads();
}

// ---------------- persistent DAG cholesky, supertasks, no global barriers ----------------
__global__ void __launch_bounds__(NTHR, 1) chol_kernel() {
    extern __shared__ char dsm[];
    uint32_t sbase = s2u(dsm);
    __shared__ float invd[128];
    __shared__ float rowbuf[128];
    __shared__ int s_t;
    __shared__ int s_e;

    int tid = threadIdx.x;
    int lane = tid & 31, warp = tid >> 5;
    int wm = warp & 3, wn = warp >> 2;

    if (tid == 0) s_e = atomicAdd(&g_ecnt, 1) / GRID_CHOL + 1;
    __syncthreads();
    int e = s_e;

    int T_total = 0;
    for (int k = 0; k < NB - 1; k++) { int SR, S; col_counts(k, SR, S); T_total += SR + S; }
    int base = (e - 1) * (T_total + GRID_CHOL);

    if (blockIdx.x == 0) {
        potf_block(0, (float*)dsm, invd, rowbuf);
        __threadfence();
        __syncthreads();
        if (tid == 0) atomicAdd(&g_dflag[0], 1);
    }

    volatile int* vtf = (volatile int*)g_tflag;
    volatile int* vuc = (volatile int*)g_ucnt;
    volatile int* vdf = (volatile int*)g_dflag;

    while (true) {
        if (tid == 0) s_t = atomicAdd(&g_next, 1) - base;
        __syncthreads();
        int t = s_t;
        if (t >= T_total) break;

        // decode column
        int k = 0, SR, S;
        for (;; k++) { col_counts(k, SR, S); if (t < SR + S) break; t -= SR + S; }
        int nb = NB - 1 - k;

        float acc[4][4][4];
#pragma unroll
        for (int mt = 0; mt < 4; mt++)
#pragma unroll
            for (int nt = 0; nt < 4; nt++)
#pragma unroll
                for (int x = 0; x < 4; x++) acc[mt][nt][x] = 0.f;

        if (t < SR) {
            // ===== trsm supertask: rows i0,(i1) => P = M * W^T =====
            int g = t;
            int i0 = k + 1 + 2 * g;
            bool has2 = (2 * g + 1 <= nb - 1);
            int i1 = i0 + (has2 ? 1 : 0);
            int rmask = has2 ? 255 : 127;

            if (tid == 0) {
                while (vdf[k] < e) __nanosleep(32);
                int need = (e - 1) * k + k;
                while (vuc[i0 * NB + k] < need) __nanosleep(32);
                if (has2) while (vuc[i1 * NB + k] < need) __nanosleep(32);
            }
            __syncthreads();
            __threadfence();

            // stage W (async) + split A fp32 (sync)
            size_t koff = (size_t)k * B * B;
            stage_B(g_W0 + koff, g_W1 + koff, B, sbase, tid);
            asm volatile("cp.async.commit_group;");
            const float* Afp = g_A + (size_t)(i0 * B) * N + (size_t)k * B;
#pragma unroll
            for (int i = 0; i < 16; i++) {
                int u = tid + (i << 9);       // float4 unit over 256x32
                int r = u >> 5;
                int c4 = (u & 31) * 4;
                float4 v = *(const float4*)(Afp + (size_t)(r & rmask) * N + c4);
                __half a0, a1, b0, b1, c0, c1, d0, d1;
                split2(v.x, a0, a1); split2(v.y, b0, b1);
                split2(v.z, c0, c1); split2(v.w, d0, d1);
                __half2* p0 = (__half2*)(dsm + A0_OFF + (uint32_t)r * SP + c4 * 2);
                p0[0] = __halves2half2(a0, b0); p0[1] = __halves2half2(c0, d0);
                __half2* p1 = (__half2*)(dsm + A1_OFF + (uint32_t)r * SP + c4 * 2);
                p1[0] = __halves2half2(a1, b1); p1[1] = __halves2half2(c1, d1);
            }
            asm volatile("cp.async.wait_group 0;" ::: "memory");
            __syncthreads();
            compute_tile(sbase, lane, wm, wn, acc);
            __syncthreads();

            // epilogue: write fp32 P + fp16 splits
#pragma unroll
            for (int mt = 0; mt < 4; mt++) {
#pragma unroll
                for (int nt = 0; nt < 4; nt++) {
                    int lr = wm * 64 + mt * 16 + (lane >> 2);
                    int lc = wn * 32 + nt * 8 + (lane & 3) * 2;
#pragma unroll
                    for (int h = 0; h < 2; h++) {
                        int lrr = lr + h * 8;
                        int ta = lrr >> 7;
                        if (ta == 1 && !has2) continue;
                        size_t off = (size_t)((i0 + ta) * B + (lrr & 127)) * N + (size_t)k * B + lc;
                        float vx = acc[mt][nt][h * 2], vy = acc[mt][nt][h * 2 + 1];
                        *(float2*)(g_A + off) = make_float2(vx, vy);
                        __half x0, x1, y0, y1;
                        split2(vx, x0, x1); split2(vy, y0, y1);
                        *(__half2*)(g_L0 + off) = __halves2half2(x0, y0);
                        *(__half2*)(g_L1 + off) = __halves2half2(x1, y1);
                    }
                }
            }
            __threadfence();
            __syncthreads();
            if (tid == 0) {
                atomicAdd(&g_tflag[k * NB + i0], 1);
                if (has2) atomicAdd(&g_tflag[k * NB + i1], 1);
            }
        } else {
            // ===== syrk supertask: rows (r0,r1) x col tile b =====
            int s = t - SR;
            int g = 0;
            for (;;) { int c = min(2 * g + 2, nb); if (s < c) break; s -= c; g++; }
            int b = k + 1 + s;
            int r0 = k + 1 + 2 * g;
            bool has2 = (2 * g + 1 <= nb - 1);
            int r1 = r0 + (has2 ? 1 : 0);
            bool tile0 = (b <= r0);
            int rmask = has2 ? 255 : 127;
            bool dodiag = (g == 0 && s == 0);

            if (tid == 0) {
                while (vtf[k * NB + r0] < e) __nanosleep(32);
                if (has2) while (vtf[k * NB + r1] < e) __nanosleep(32);
                while (vtf[k * NB + b] < e) __nanosleep(32);
            }
            __syncthreads();
            __threadfence();

            size_t aoff = (size_t)(r0 * B) * N + (size_t)k * B;
            size_t boff = (size_t)(b * B) * N + (size_t)k * B;
            stage_A(g_L0 + aoff, g_L1 + aoff, rmask, sbase, tid);
            stage_B(g_L0 + boff, g_L1 + boff, N, sbase, tid);
            asm volatile("cp.async.commit_group;");
            asm volatile("cp.async.wait_group 0;" ::: "memory");
            __syncthreads();
            compute_tile(sbase, lane, wm, wn, acc);

            // serialize cross-column RMW on C tiles
            if (tid == 0) {
                int need = (e - 1) * b + k;
                if (tile0) while (vuc[r0 * NB + b] < need) __nanosleep(32);
                if (has2)  while (vuc[r1 * NB + b] < need) __nanosleep(32);
            }
            __syncthreads();
            __threadfence();

#pragma unroll
            for (int mt = 0; mt < 4; mt++) {
#pragma unroll
                for (int nt = 0; nt < 4; nt++) {
                    int lr = wm * 64 + mt * 16 + (lane >> 2);
                    int lc = wn * 32 + nt * 8 + (lane & 3) * 2;
#pragma unroll
                    for (int h = 0; h < 2; h++) {
                        int lrr = lr + h * 8;
                        int ta = lrr >> 7;
                        if (ta == 0 ? !tile0 : !has2) continue;
                        size_t off = (size_t)((r0 + ta) * B + (lrr & 127)) * N + (size_t)b * B + lc;
                        float2 c = *(float2*)(g_A + off);
                        c.x -= acc[mt][nt][h * 2];
                        c.y -= acc[mt][nt][h * 2 + 1];
                        *(float2*)(g_A + off) = c;
                    }
                }
            }
            __threadfence();
            __syncthreads();
            if (tid == 0) {
                if (tile0) atomicAdd(&g_ucnt[r0 * NB + b], 1);
                if (has2)  atomicAdd(&g_ucnt[r1 * NB + b], 1);
            }
            if (dodiag) {
                __syncthreads();
                potf_block(k + 1, (float*)dsm, invd, rowbuf);
                __threadfence();
                __syncthreads();
                if (tid == 0) atomicAdd(&g_dflag[k + 1], 1);
            }
        }
        __syncthreads();
    }
}

// ---------------- spin-chained forward solve (epoch-safe) ----------------
__global__ void __launch_bounds__(512, 1) fwd_solve() {
    int k = blockIdx.x;
    int tid = threadIdx.x;
    int t = tid & 127, q = tid >> 7;
    __shared__ float svec[128];
    __shared__ float red[512];
    __shared__ int s_e;
    if (tid == 0) s_e = atomicAdd(&g_fep, 1) / NB + 1;
    __syncthreads();
    int e = s_e;
    float acc = (q == 0) ? g_r[k * B + t] : 0.f;
    for (int j = 0; j < k; j++) {
        if (tid == 0) { while (((volatile int*)g_ff)[j] < e) __nanosleep(32); }
        __syncthreads();
        __threadfence();
        if (tid < 128) svec[tid] = g_zsol[j * B + tid];
        __syncthreads();
        const float* Lr = g_A + (size_t)(k * B + t) * N + (size_t)j * B + q * 32;
        float a0 = 0.f, a1 = 0.f;
#pragma unroll
        for (int c = 0; c < 32; c += 8) {
            float4 l0 = *(const float4*)(Lr + c);
            float4 l1 = *(const float4*)(Lr + c + 4);
            int cc = q * 32 + c;
            a0 += l0.x * svec[cc] + l0.y * svec[cc + 1] + l0.z * svec[cc + 2] + l0.w * svec[cc + 3];
            a1 += l1.x * svec[cc + 4] + l1.y * svec[cc + 5] + l1.z * svec[cc + 6] + l1.w * svec[cc + 7];
        }
        acc -= a0 + a1;
        __syncthreads();
    }
    red[q * 128 + t] = acc;
    __syncthreads();
    if (tid < 128) svec[tid] = red[tid] + red[128 + tid] + red[256 + tid] + red[384 + tid];
    __syncthreads();
    const float* Wr = g_invL + (size_t)k * B * B + (size_t)t * B + q * 32;
    float z = 0.f;
#pragma unroll
    for (int c = 0; c < 32; c += 4) {
        float4 w = *(const float4*)(Wr + c);
        int cc = q * 32 + c;
        z += w.x * svec[cc] + w.y * svec[cc + 1] + w.z * svec[cc + 2] + w.w * svec[cc + 3];
    }
    red[q * 128 + t] = z;
    __syncthreads();
    if (tid < 128) g_zsol[k * B + tid] = red[tid] + red[128 + tid] + red[256 + tid] + red[384 + tid];
    __threadfence();
    __syncthreads();
    if (tid == 0) atomicAdd(&g_ff[k], 1);
}

// ---------------- spin-chained backward solve (epoch-safe) ----------------
__global__ void __launch_bounds__(512, 1) bwd_solve() {
    int k = NB - 1 - blockIdx.x;
    int tid = threadIdx.x;
    int t = tid & 127, q = tid >> 7;
    __shared__ float svec[128];
    __shared__ float red[512];
    __shared__ int s_e;
    if (tid == 0) s_e = atomicAdd(&g_bep, 1) / NB + 1;
    __syncthreads();
    int e = s_e;
    float acc = (q == 0) ? g_zsol[k * B + t] : 0.f;
    for (int j = k + 1; j < NB; j++) {
        if (tid == 0) { while (((volatile int*)g_fb)[j] < e) __nanosleep(32); }
        __syncthreads();
        __threadfence();
        if (tid < 128) svec[tid] = g_alpha[j * B + tid];
        __syncthreads();
        const float* Lc = g_A + (size_t)(j * B + q * 32) * N + (size_t)k * B + t;
        float a0 = 0.f, a1 = 0.f, a2 = 0.f, a3 = 0.f;
#pragma unroll
        for (int r = 0; r < 32; r += 4) {
            int rr = q * 32 + r;
            a0 += Lc[(size_t)(r + 0) * N] * svec[rr + 0];
            a1 += Lc[(size_t)(r + 1) * N] * svec[rr + 1];
            a2 += Lc[(size_t)(r + 2) * N] * svec[rr + 2];
            a3 += Lc[(size_t)(r + 3) * N] * svec[rr + 3];
        }
        acc -= ((a0 + a1) + (a2 + a3));
        __syncthreads();
    }
    red[q * 128 + t] = acc;
    __syncthreads();
    if (tid < 128) svec[tid] = red[tid] + red[128 + tid] + red[256 + tid] + red[384 + tid];
    __syncthreads();
    const float* Wc = g_invL + (size_t)k * B * B + (size_t)(q * 32) * B + t;
    float al = 0.f;
#pragma unroll 8
    for (int r = 0; r < 32; r++) al += Wc[(size_t)r * B] * svec[q * 32 + r];
    red[q * 128 + t] = al;
    __syncthreads();
    if (tid < 128) g_alpha[k * B + tid] = red[tid] + red[128 + tid] + red[256 + tid] + red[384 + tid];
    __threadfence();
    __syncthreads();
    if (tid == 0) atomicAdd(&g_fb[k], 1);
}

// ---------------- fused predict ----------------
__global__ void __launch_bounds__(256, 2) predict_kernel(const float* __restrict__ Xte,
                                                         const float* __restrict__ Xtr,
                                                         float* __restrict__ out) {
    __shared__ float sTr[32 * 132];
    __shared__ float sAl[128], sXX[128];
    __shared__ float sRed[256];
    int tid = threadIdx.x;
    int rl = tid >> 3, sl = tid & 7;
    int grow = blockIdx.x * 32 + rl;

    float xt[32];
#pragma unroll
    for (int dg = 0; dg < 8; dg++)
        *(float4*)(xt + dg * 4) = *(const float4*)(Xte + (size_t)grow * D + dg * 4);
    float xxt = 0.f;
#pragma unroll
    for (int d = 0; d < 32; d++) xxt += xt[d] * xt[d];

    float acc = 0.f;
    for (int ch = 0; ch < N / 128; ch++) {
        int pbase = ch * 128;
        __syncthreads();
#pragma unroll
        for (int i = 0; i < 4; i++) {
            int f = tid + i * 256;
            int p = f >> 3;
            int dg = (f & 7) << 2;
            float4 v = *(const float4*)(Xtr + (size_t)(pbase + p) * D + dg);
            sTr[(dg + 0) * 132 + p] = v.x; sTr[(dg + 1) * 132 + p] = v.y;
            sTr[(dg + 2) * 132 + p] = v.z; sTr[(dg + 3) * 132 + p] = v.w;
        }
        if (tid < 128) { sAl[tid] = g_alpha[pbase + tid]; sXX[tid] = g_xx[pbase + tid]; }
        __syncthreads();
#pragma unroll 4
        for (int i = 0; i < 16; i++) {
            int p = i * 8 + sl;
            float dot = 0.f;
#pragma unroll
            for (int d = 0; d < 32; d++) dot += xt[d] * sTr[d * 132 + p];
            float sq = fmaxf(xxt + sXX[p] - 2.f * dot, 0.f);
            acc += __expf(-GAMMA * sq) * sAl[p];
        }
    }
    sRed[rl * 8 + sl] = acc;
    __syncthreads();
    if (tid < 32) {
        float s = 0.f;
#pragma unroll
        for (int j = 0; j < 8; j++) s += sRed[tid * 8 + j];
        out[blockIdx.x * 32 + tid] = s;
    }
}

// ---------------- launcher ----------------
extern "C" void kernel_launch(void* const* d_in, const int* in_sizes, int n_in,
                              void* d_out, int out_size) {
    const float* Xtr = (const float*)d_in[0];
    const float* y   = (const float*)d_in[1];
    const float* Xte = (const float*)d_in[2];
    float* out = (float*)d_out;

    cudaFuncSetAttribute(chol_kernel, cudaFuncAttributeMaxDynamicSharedMemorySize, CHOL_DYN);

    prep_kernel<<<N / 256, 256>>>(Xtr, y);
    build_kernel<<<NB * (NB + 1) / 2, 256>>>(Xtr);
    noop_kernel<<<1, 1>>>();
    chol_kernel<<<GRID_CHOL, NTHR, CHOL_DYN>>>();
    fwd_solve<<<NB, 512>>>();
    bwd_solve<<<NB, 512>>>();
    predict_kernel<<<N / 32, 256>>>(Xte, Xtr, out);
}

// round 14
// speedup vs baseline: 1.0821x; 1.0821x over previous
#include <cuda_runtime.h>
#include <cuda_fp16.h>
#include <math.h>
#include <stdint.h>

#define N 8192
#define D 32
#define NB 64
#define B 128
#define GAMMA 0.03125f
#define REG 1e-3f
#define GRID_CHOL 148
#define NTHR 512
#define SP 272u                  // fp16 operand pitch (bytes)
#define A0_OFF 0u
#define A1_OFF 34816u
#define B0_OFF 69632u
#define B1_OFF 104448u
#define SC_OFF 139264u           // fp32 C tile, pitch 132 floats (528B)
#define CHOL_DYN 206848u         // SC_OFF + 128*528

// ---------------- device scratch ----------------
__device__ float g_A[(size_t)N * N];
__device__ float g_invL[(size_t)NB * B * B];
__device__ __align__(16) __half g_L0[(size_t)N * N];
__device__ __align__(16) __half g_L1[(size_t)N * N];
__device__ __align__(16) __half g_W0[(size_t)NB * B * B];
__device__ __align__(16) __half g_W1[(size_t)NB * B * B];
__device__ float g_xx[N];
__device__ float g_r[N];
__device__ float g_zsol[N];
__device__ float g_alpha[N];
// epoch-accumulating sync state (never reset)
__device__ int g_tflag[NB * NB];
__device__ int g_cnt[NB];
__device__ int g_done[NB + 1];
__device__ int g_ecnt;
__device__ int g_ff[NB];
__device__ int g_fb[NB];
__device__ int g_fep;
__device__ int g_bep;

// ---------------- helpers ----------------
__device__ __forceinline__ uint32_t s2u(const void* p) {
    uint32_t a;
    asm("{ .reg .u64 t; cvta.to.shared.u64 t, %1; cvt.u32.u64 %0, t; }" : "=r"(a) : "l"(p));
    return a;
}
__device__ __forceinline__ void ldsm_x4(uint32_t* d, uint32_t addr) {
    asm volatile("ldmatrix.sync.aligned.m8n8.x4.shared.b16 {%0,%1,%2,%3}, [%4];"
        : "=r"(d[0]), "=r"(d[1]), "=r"(d[2]), "=r"(d[3]) : "r"(addr));
}
__device__ __forceinline__ void ldsm_x2(uint32_t* d, uint32_t addr) {
    asm volatile("ldmatrix.sync.aligned.m8n8.x2.shared.b16 {%0,%1}, [%2];"
        : "=r"(d[0]), "=r"(d[1]) : "r"(addr));
}
__device__ __forceinline__ void mma16816(float* c, const uint32_t* a, const uint32_t* b) {
    asm volatile("mma.sync.aligned.m16n8k16.row.col.f32.f16.f16.f32 "
        "{%0,%1,%2,%3}, {%4,%5,%6,%7}, {%8,%9}, {%0,%1,%2,%3};"
        : "+f"(c[0]), "+f"(c[1]), "+f"(c[2]), "+f"(c[3])
        : "r"(a[0]), "r"(a[1]), "r"(a[2]), "r"(a[3]), "r"(b[0]), "r"(b[1]));
}
__device__ __forceinline__ void cpasync16(uint32_t saddr, const void* g) {
    asm volatile("cp.async.cg.shared.global [%0], [%1], 16;" :: "r"(saddr), "l"(g));
}
__device__ __forceinline__ void split2(float x, __half& h0, __half& h1) {
    h0 = __float2half_rn(x);
    h1 = __float2half_rn(x - __half2float(h0));
}
__device__ __forceinline__ void tri_decode_row(int p, int& ti, int& tj) {
    float pf = sqrtf(8.f * (float)p + 1.f);
    int i = (int)((pf - 1.f) * 0.5f);
    while ((i + 1) * (i + 2) / 2 <= p) i++;
    while (i * (i + 1) / 2 > p) i--;
    ti = i; tj = p - i * (i + 1) / 2;
}

__global__ void noop_kernel() {}

// ---------------- prep ----------------
__global__ void prep_kernel(const float* __restrict__ Xtr, const float* __restrict__ y) {
    int i = blockIdx.x * 256 + threadIdx.x;
    float s = 0.f;
#pragma unroll
    for (int dg = 0; dg < 8; dg++) {
        float4 v = *(const float4*)(Xtr + (size_t)i * D + dg * 4);
        s += v.x * v.x + v.y * v.y + v.z * v.z + v.w * v.w;
    }
    g_xx[i] = s;
    g_r[i] = y[i];
}

// ---------------- build gram (lower triangle of 128-blocks) ----------------
__global__ void __launch_bounds__(256, 2) build_kernel(const float* __restrict__ Xtr) {
    __shared__ float sXi[32 * 132];
    __shared__ float sXj[32 * 132];
    __shared__ float sxxi[128], sxxj[128];
    int tid = threadIdx.x;
    int bi, bj;
    tri_decode_row(blockIdx.x, bi, bj);

#pragma unroll
    for (int i = 0; i < 4; i++) {
        int f = tid + i * 256;
        int r = f >> 3;
        int dg = (f & 7) << 2;
        float4 v = *(const float4*)(Xtr + (size_t)(bi * B + r) * D + dg);
        sXi[(dg + 0) * 132 + r] = v.x; sXi[(dg + 1) * 132 + r] = v.y;
        sXi[(dg + 2) * 132 + r] = v.z; sXi[(dg + 3) * 132 + r] = v.w;
        float4 w = *(const float4*)(Xtr + (size_t)(bj * B + r) * D + dg);
        sXj[(dg + 0) * 132 + r] = w.x; sXj[(dg + 1) * 132 + r] = w.y;
        sXj[(dg + 2) * 132 + r] = w.z; sXj[(dg + 3) * 132 + r] = w.w;
    }
    if (tid < 128) { sxxi[tid] = g_xx[bi * B + tid]; sxxj[tid] = g_xx[bj * B + tid]; }
    __syncthreads();

    int tm = tid >> 4, tn = tid & 15;
    float acc[8][8];
#pragma unroll
    for (int i = 0; i < 8; i++)
#pragma unroll
        for (int j = 0; j < 8; j++) acc[i][j] = 0.f;

#pragma unroll
    for (int d = 0; d < 32; d++) {
        float a[8], b[8];
        *(float4*)(a)     = *(const float4*)(&sXi[d * 132 + tm * 8]);
        *(float4*)(a + 4) = *(const float4*)(&sXi[d * 132 + tm * 8 + 4]);
        *(float4*)(b)     = *(const float4*)(&sXj[d * 132 + tn * 8]);
        *(float4*)(b + 4) = *(const float4*)(&sXj[d * 132 + tn * 8 + 4]);
#pragma unroll
        for (int i = 0; i < 8; i++)
#pragma unroll
            for (int j = 0; j < 8; j++) acc[i][j] += a[i] * b[j];
    }

#pragma unroll
    for (int i = 0; i < 8; i++) {
        int li = tm * 8 + i;
        int gi = bi * B + li;
        float v[8];
#pragma unroll
        for (int j = 0; j < 8; j++) {
            int lj = tn * 8 + j;
            int gj = bj * B + lj;
            float sq = sxxi[li] + sxxj[lj] - 2.f * acc[i][j];
            sq = fmaxf(sq, 0.f);
            float val = __expf(-GAMMA * sq);
            if (gi == gj) val += REG;
            v[j] = val;
        }
        float* cp = g_A + (size_t)gi * N + bj * B + tn * 8;
        *(float4*)(cp)     = make_float4(v[0], v[1], v[2], v[3]);
        *(float4*)(cp + 4) = make_float4(v[4], v[5], v[6], v[7]);
    }
}

// ---------------- staging: one operand (both splits), full K=128 ----------------
__device__ __forceinline__ void stage_op(const __half* p0, const __half* p1, int ld,
                                         uint32_t dst0, uint32_t dst1, int tid) {
#pragma unroll
    for (int i = 0; i < 8; i++) {
        int f = tid + (i << 9);       // 0..4095
        int s = f >> 11;
        int rem = f & 2047;
        int r = rem >> 4;
        int seg = rem & 15;
        const __half* p = s ? p1 : p0;
        cpasync16((s ? dst1 : dst0) + (uint32_t)r * SP + seg * 16,
                  p + (size_t)r * ld + seg * 8);
    }
}
// prefetch fp32 C tile into smem (pitch 132 floats)
__device__ __forceinline__ void stage_C(const float* Cg, uint32_t dst, int tid) {
#pragma unroll
    for (int i = 0; i < 8; i++) {
        int f = tid + (i << 9);
        int r = f >> 5;
        int seg = f & 31;
        cpasync16(dst + (uint32_t)r * 528 + seg * 16, Cg + (size_t)r * N + seg * 4);
    }
}

// ---------------- compute full-K 128x128 tile, fp16x2 (3 products), no syncs ----------------
__device__ __forceinline__ void compute_tile(uint32_t sbase, int lane, int wm, int wn,
                                             float acc[2][4][4]) {
#pragma unroll
    for (int kt = 0; kt < 8; kt++) {
#pragma unroll
        for (int sb = 0; sb < 2; sb++) {
            uint32_t bfr[4][2];
#pragma unroll
            for (int nt = 0; nt < 4; nt++) {
                int n = wn * 32 + nt * 8 + (lane & 7);
                int col = kt * 16 + ((lane >> 3) & 1) * 8;
                ldsm_x2(bfr[nt], sbase + (sb ? B1_OFF : B0_OFF) + (uint32_t)n * SP + col * 2);
            }
#pragma unroll
            for (int sa = 0; sa < 2; sa++) {
                if (sa + sb > 1) continue;
                uint32_t af[2][4];
#pragma unroll
                for (int mt = 0; mt < 2; mt++) {
                    int rrow = wm * 32 + mt * 16 + (lane & 15);
                    int col = kt * 16 + (lane >> 4) * 8;
                    ldsm_x4(af[mt], sbase + (sa ? A1_OFF : A0_OFF) + (uint32_t)rrow * SP + col * 2);
                }
#pragma unroll
                for (int mt = 0; mt < 2; mt++)
#pragma unroll
                    for (int nt = 0; nt < 4; nt++)
                        mma16816(acc[mt][nt], af[mt], bfr[nt]);
            }
        }
    }
}

// ---------------- potf: factor diag block kb, write invL + fp16 splits (512 thr) ----------------
__device__ void potf_block(int kb, float* sD, float* invd, float* rowbuf) {
    int tid = threadIdx.x;
    size_t base = (size_t)(kb * B) * N + (size_t)kb * B;

    for (int idx = tid; idx < B * B; idx += NTHR) {
        int r = idx >> 7, c = idx & 127;
        sD[r * 129 + c] = g_A[base + (size_t)r * N + c];
    }
    __syncthreads();

    int tr = tid & 31, tj2 = tid >> 5;
    for (int c = 0; c < B - 1; c++) {
        float ipiv = __fdividef(1.f, sD[c * 129 + c]);
        for (int r = c + 1 + tr; r < B; r += 32) {
            float a = sD[r * 129 + c] * ipiv;
            for (int jj = c + 1 + tj2; jj <= r; jj += 16)
                sD[r * 129 + jj] -= a * sD[jj * 129 + c];
        }
        __syncthreads();
    }
    for (int c = tid; c < B; c += NTHR) invd[c] = rsqrtf(sD[c * 129 + c]);
    __syncthreads();
    for (int idx = tid; idx < B * B; idx += NTHR) {
        int r = idx >> 7, c = idx & 127;
        if (c < r) sD[r * 129 + c] *= invd[c];
        else if (c == r) sD[r * 129 + c] = invd[c];
    }
    __syncthreads();

    for (int r = 1; r < B; r++) {
        for (int c = tid; c < r; c += NTHR) rowbuf[c] = sD[r * 129 + c];
        __syncthreads();
        if (tid < r) {
            int c = tid;
            float a0 = 0.f, a1 = 0.f, a2 = 0.f, a3 = 0.f;
            int jj = c;
            for (; jj + 3 < r; jj += 4) {
                a0 += rowbuf[jj]     * sD[jj * 129 + c];
                a1 += rowbuf[jj + 1] * sD[(jj + 1) * 129 + c];
                a2 += rowbuf[jj + 2] * sD[(jj + 2) * 129 + c];
                a3 += rowbuf[jj + 3] * sD[(jj + 3) * 129 + c];
            }
            for (; jj < r; jj++) a0 += rowbuf[jj] * sD[jj * 129 + c];
            sD[r * 129 + c] = -invd[r] * ((a0 + a1) + (a2 + a3));
        }
        __syncthreads();
    }
    size_t koff = (size_t)kb * B * B;
    for (int idx = tid; idx < B * B; idx += NTHR) {
        int r = idx >> 7, c = idx & 127;
        float w = (c <= r) ? sD[r * 129 + c] : 0.f;
        g_invL[koff + idx] = w;
        __half h0, h1;
        split2(w, h0, h1);
        g_W0[koff + idx] = h0;
        g_W1[koff + idx] = h1;
    }
    __syncthreads();
}

// ---------------- persistent right-looking cholesky (epoch-safe, full-K tiles) ----------------
__device__ __forceinline__ void barrier_phase(int pid, int epoch) {
    __syncthreads();
    if (threadIdx.x == 0) {
        __threadfence();
        atomicAdd(&g_done[pid], 1);
        while (((volatile int*)g_done)[pid] < epoch * GRID_CHOL) __nanosleep(64);
        __threadfence();
    }
    __syncthreads();
}

__global__ void __launch_bounds__(NTHR, 1) chol_kernel() {
    extern __shared__ char dsm[];
    uint32_t sbase = s2u(dsm);
    float* sC = (float*)(dsm + SC_OFF);
    __shared__ float invd[128];
    __shared__ float rowbuf[128];
    __shared__ int s_t;
    __shared__ int s_e;

    int tid = threadIdx.x;
    int lane = tid & 31, warp = tid >> 5;
    int wm = warp & 3, wn = warp >> 2;

    if (tid == 0) s_e = atomicAdd(&g_ecnt, 1) / GRID_CHOL + 1;
    __syncthreads();
    int epoch = s_e;

    if (blockIdx.x == 0) potf_block(0, (float*)dsm, invd, rowbuf);
    barrier_phase(NB, epoch);

    for (int k = 0; k < NB - 1; k++) {
        int nb = NB - 1 - k;
        int ntask = nb + nb * (nb + 1) / 2;
        int base = (epoch - 1) * (ntask + GRID_CHOL);
        volatile int* tf = (volatile int*)(g_tflag + k * NB);
        size_t koff = (size_t)k * B * B;

        while (true) {
            if (tid == 0) s_t = atomicAdd(&g_cnt[k], 1) - base;
            __syncthreads();
            int t = s_t;
            if (t >= ntask) break;

            float acc[2][4][4];
#pragma unroll
            for (int mt = 0; mt < 2; mt++)
#pragma unroll
                for (int nt = 0; nt < 4; nt++)
#pragma unroll
                    for (int x = 0; x < 4; x++) acc[mt][nt][x] = 0.f;

            if (t < nb) {
                // ===== trsm tile (i,k): P = M * W^T =====
                int i = k + 1 + t;
                float* Pg = g_A + (size_t)(i * B) * N + (size_t)k * B;
                stage_op(g_W0 + koff, g_W1 + koff, B, sbase + B0_OFF, sbase + B1_OFF, tid);
                asm volatile("cp.async.commit_group;");
                // split fp32 A -> A0/A1 smem
#pragma unroll
                for (int q = 0; q < 8; q++) {
                    int f = tid + (q << 9);
                    int r = f >> 5;
                    int c4 = (f & 31) * 4;
                    float4 v = *(const float4*)(Pg + (size_t)r * N + c4);
                    __half a0, a1, b0, b1, c0, c1, d0, d1;
                    split2(v.x, a0, a1); split2(v.y, b0, b1);
                    split2(v.z, c0, c1); split2(v.w, d0, d1);
                    __half2* p0 = (__half2*)(dsm + A0_OFF + (uint32_t)r * SP + c4 * 2);
                    p0[0] = __halves2half2(a0, b0); p0[1] = __halves2half2(c0, d0);
                    __half2* p1 = (__half2*)(dsm + A1_OFF + (uint32_t)r * SP + c4 * 2);
                    p1[0] = __halves2half2(a1, b1); p1[1] = __halves2half2(c1, d1);
                }
                asm volatile("cp.async.wait_group 0;" ::: "memory");
                __syncthreads();
                compute_tile(sbase, lane, wm, wn, acc);
                // stage acc into sC area (as sE) then coalesced writeout
#pragma unroll
                for (int mt = 0; mt < 2; mt++)
#pragma unroll
                    for (int nt = 0; nt < 4; nt++) {
                        int lr = wm * 32 + mt * 16 + (lane >> 2);
                        int lc = wn * 32 + nt * 8 + (lane & 3) * 2;
                        sC[lr * 132 + lc]           = acc[mt][nt][0];
                        sC[lr * 132 + lc + 1]       = acc[mt][nt][1];
                        sC[(lr + 8) * 132 + lc]     = acc[mt][nt][2];
                        sC[(lr + 8) * 132 + lc + 1] = acc[mt][nt][3];
                    }
                __syncthreads();
#pragma unroll
                for (int q = 0; q < 8; q++) {
                    int f = tid + (q << 9);
                    int r = f >> 5;
                    int c4 = (f & 31) * 4;
                    float4 s = *(float4*)(sC + r * 132 + c4);
                    size_t off = (size_t)(i * B + r) * N + (size_t)k * B + c4;
                    *(float4*)(g_A + off) = s;
                    __half x0, x1, y0, y1, z0, z1, w0, w1;
                    split2(s.x, x0, x1); split2(s.y, y0, y1);
                    split2(s.z, z0, z1); split2(s.w, w0, w1);
                    *(__half2*)(g_L0 + off)     = __halves2half2(x0, y0);
                    *(__half2*)(g_L0 + off + 2) = __halves2half2(z0, w0);
                    *(__half2*)(g_L1 + off)     = __halves2half2(x1, y1);
                    *(__half2*)(g_L1 + off + 2) = __halves2half2(z1, w1);
                }
                __threadfence();
                __syncthreads();
                if (tid == 0) atomicAdd(&g_tflag[k * NB + i], 1);
            } else {
                // ===== syrk tile (a,b) -= L(a,k) * L(b,k)^T =====
                int p, q2;
                tri_decode_row(t - nb, p, q2);
                int a = k + 1 + p, b = k + 1 + q2;
                if (tid == 0) {
                    while (tf[a] < epoch) __nanosleep(32);
                    while (tf[b] < epoch) __nanosleep(32);
                }
                __syncthreads();
                __threadfence();
                size_t aoff = (size_t)(a * B) * N + (size_t)k * B;
                size_t boff = (size_t)(b * B) * N + (size_t)k * B;
                float* Cg = g_A + (size_t)(a * B) * N + (size_t)b * B;
                stage_op(g_L0 + aoff, g_L1 + aoff, N, sbase + A0_OFF, sbase + A1_OFF, tid);
                stage_op(g_L0 + boff, g_L1 + boff, N, sbase + B0_OFF, sbase + B1_OFF, tid);
                asm volatile("cp.async.commit_group;");
                stage_C(Cg, sbase + SC_OFF, tid);
                asm volatile("cp.async.commit_group;");
                asm volatile("cp.async.wait_group 1;" ::: "memory");   // operands ready
                __syncthreads();
                compute_tile(sbase, lane, wm, wn, acc);
                asm volatile("cp.async.wait_group 0;" ::: "memory");   // C ready
                __syncthreads();
                // RMW in smem
#pragma unroll
                for (int mt = 0; mt < 2; mt++)
#pragma unroll
                    for (int nt = 0; nt < 4; nt++) {
                        int lr = wm * 32 + mt * 16 + (lane >> 2);
                        int lc = wn * 32 + nt * 8 + (lane & 3) * 2;
                        sC[lr * 132 + lc]           -= acc[mt][nt][0];
                        sC[lr * 132 + lc + 1]       -= acc[mt][nt][1];
                        sC[(lr + 8) * 132 + lc]     -= acc[mt][nt][2];
                        sC[(lr + 8) * 132 + lc + 1] -= acc[mt][nt][3];
                    }
                __syncthreads();
#pragma unroll
                for (int q = 0; q < 8; q++) {
                    int f = tid + (q << 9);
                    int r = f >> 5;
                    int c4 = (f & 31) * 4;
                    *(float4*)(Cg + (size_t)r * N + c4) = *(float4*)(sC + r * 132 + c4);
                }
                if (t == nb) {
                    __syncthreads();
                    potf_block(k + 1, (float*)dsm, invd, rowbuf);
                }
            }
            __syncthreads();
        }
        barrier_phase(k, epoch);
    }
}

// ---------------- spin-chained forward solve (epoch-safe) ----------------
__global__ void __launch_bounds__(512, 1) fwd_solve() {
    int k = blockIdx.x;
    int tid = threadIdx.x;
    int t = tid & 127, q = tid >> 7;
    __shared__ float svec[128];
    __shared__ float red[512];
    __shared__ int s_e;
    if (tid == 0) s_e = atomicAdd(&g_fep, 1) / NB + 1;
    __syncthreads();
    int e = s_e;
    float acc = (q == 0) ? g_r[k * B + t] : 0.f;
    for (int j = 0; j < k; j++) {
        if (tid == 0) { while (((volatile int*)g_ff)[j] < e) __nanosleep(32); }
        __syncthreads();
        __threadfence();
        if (tid < 128) svec[tid] = g_zsol[j * B + tid];
        __syncthreads();
        const float* Lr = g_A + (size_t)(k * B + t) * N + (size_t)j * B + q * 32;
        float a0 = 0.f, a1 = 0.f;
#pragma unroll
        for (int c = 0; c < 32; c += 8) {
            float4 l0 = *(const float4*)(Lr + c);
            float4 l1 = *(const float4*)(Lr + c + 4);
            int cc = q * 32 + c;
            a0 += l0.x * svec[cc] + l0.y * svec[cc + 1] + l0.z * svec[cc + 2] + l0.w * svec[cc + 3];
            a1 += l1.x * svec[cc + 4] + l1.y * svec[cc + 5] + l1.z * svec[cc + 6] + l1.w * svec[cc + 7];
        }
        acc -= a0 + a1;
        __syncthreads();
    }
    red[q * 128 + t] = acc;
    __syncthreads();
    if (tid < 128) svec[tid] = red[tid] + red[128 + tid] + red[256 + tid] + red[384 + tid];
    __syncthreads();
    const float* Wr = g_invL + (size_t)k * B * B + (size_t)t * B + q * 32;
    float z = 0.f;
#pragma unroll
    for (int c = 0; c < 32; c += 4) {
        float4 w = *(const float4*)(Wr + c);
        int cc = q * 32 + c;
        z += w.x * svec[cc] + w.y * svec[cc + 1] + w.z * svec[cc + 2] + w.w * svec[cc + 3];
    }
    red[q * 128 + t] = z;
    __syncthreads();
    if (tid < 128) g_zsol[k * B + tid] = red[tid] + red[128 + tid] + red[256 + tid] + red[384 + tid];
    __threadfence();
    __syncthreads();
    if (tid == 0) atomicAdd(&g_ff[k], 1);
}

// ---------------- spin-chained backward solve (epoch-safe) ----------------
__global__ void __launch_bounds__(512, 1) bwd_solve() {
    int k = NB - 1 - blockIdx.x;
    int tid = threadIdx.x;
    int t = tid & 127, q = tid >> 7;
    __shared__ float svec[128];
    __shared__ float red[512];
    __shared__ int s_e;
    if (tid == 0) s_e = atomicAdd(&g_bep, 1) / NB + 1;
    __syncthreads();
    int e = s_e;
    float acc = (q == 0) ? g_zsol[k * B + t] : 0.f;
    for (int j = k + 1; j < NB; j++) {
        if (tid == 0) { while (((volatile int*)g_fb)[j] < e) __nanosleep(32); }
        __syncthreads();
        __threadfence();
        if (tid < 128) svec[tid] = g_alpha[j * B + tid];
        __syncthreads();
        const float* Lc = g_A + (size_t)(j * B + q * 32) * N + (size_t)k * B + t;
        float a0 = 0.f, a1 = 0.f, a2 = 0.f, a3 = 0.f;
#pragma unroll
        for (int r = 0; r < 32; r += 4) {
            int rr = q * 32 + r;
            a0 += Lc[(size_t)(r + 0) * N] * svec[rr + 0];
            a1 += Lc[(size_t)(r + 1) * N] * svec[rr + 1];
            a2 += Lc[(size_t)(r + 2) * N] * svec[rr + 2];
            a3 += Lc[(size_t)(r + 3) * N] * svec[rr + 3];
        }
        acc -= ((a0 + a1) + (a2 + a3));
        __syncthreads();
    }
    red[q * 128 + t] = acc;
    __syncthreads();
    if (tid < 128) svec[tid] = red[tid] + red[128 + tid] + red[256 + tid] + red[384 + tid];
    __syncthreads();
    const float* Wc = g_invL + (size_t)k * B * B + (size_t)(q * 32) * B + t;
    float al = 0.f;
#pragma unroll 8
    for (int r = 0; r < 32; r++) al += Wc[(size_t)r * B] * svec[q * 32 + r];
    red[q * 128 + t] = al;
    __syncthreads();
    if (tid < 128) g_alpha[k * B + tid] = red[tid] + red[128 + tid] + red[256 + tid] + red[384 + tid];
    __threadfence();
    __syncthreads();
    if (tid == 0) atomicAdd(&g_fb[k], 1);
}

// ---------------- fused predict ----------------
__global__ void __launch_bounds__(256, 2) predict_kernel(const float* __restrict__ Xte,
                                                         const float* __restrict__ Xtr,
                                                         float* __restrict__ out) {
    __shared__ float sTr[32 * 132];
    __shared__ float sAl[128], sXX[128];
    __shared__ float sRed[256];
    int tid = threadIdx.x;
    int rl = tid >> 3, sl = tid & 7;
    int grow = blockIdx.x * 32 + rl;

    float xt[32];
#pragma unroll
    for (int dg = 0; dg < 8; dg++)
        *(float4*)(xt + dg * 4) = *(const float4*)(Xte + (size_t)grow * D + dg * 4);
    float xxt = 0.f;
#pragma unroll
    for (int d = 0; d < 32; d++) xxt += xt[d] * xt[d];

    float acc = 0.f;
    for (int ch = 0; ch < N / 128; ch++) {
        int pbase = ch * 128;
        __syncthreads();
#pragma unroll
        for (int i = 0; i < 4; i++) {
            int f = tid + i * 256;
            int p = f >> 3;
            int dg = (f & 7) << 2;
            float4 v = *(const float4*)(Xtr + (size_t)(pbase + p) * D + dg);
            sTr[(dg + 0) * 132 + p] = v.x; sTr[(dg + 1) * 132 + p] = v.y;
            sTr[(dg + 2) * 132 + p] = v.z; sTr[(dg + 3) * 132 + p] = v.w;
        }
        if (tid < 128) { sAl[tid] = g_alpha[pbase + tid]; sXX[tid] = g_xx[pbase + tid]; }
        __syncthreads();
#pragma unroll 4
        for (int i = 0; i < 16; i++) {
            int p = i * 8 + sl;
            float dot = 0.f;
#pragma unroll
            for (int d = 0; d < 32; d++) dot += xt[d] * sTr[d * 132 + p];
            float sq = fmaxf(xxt + sXX[p] - 2.f * dot, 0.f);
            acc += __expf(-GAMMA * sq) * sAl[p];
        }
    }
    sRed[rl * 8 + sl] = acc;
    __syncthreads();
    if (tid < 32) {
        float s = 0.f;
#pragma unroll
        for (int j = 0; j < 8; j++) s += sRed[tid * 8 + j];
        out[blockIdx.x * 32 + tid] = s;
    }
}

// ---------------- launcher ----------------
extern "C" void kernel_launch(void* const* d_in, const int* in_sizes, int n_in,
                              void* d_out, int out_size) {
    const float* Xtr = (const float*)d_in[0];
    const float* y   = (const float*)d_in[1];
    const float* Xte = (const float*)d_in[2];
    float* out = (float*)d_out;

    cudaFuncSetAttribute(chol_kernel, cudaFuncAttributeMaxDynamicSharedMemorySize, CHOL_DYN);

    prep_kernel<<<N / 256, 256>>>(Xtr, y);
    build_kernel<<<NB * (NB + 1) / 2, 256>>>(Xtr);
    noop_kernel<<<1, 1>>>();
    chol_kernel<<<GRID_CHOL, NTHR, CHOL_DYN>>>();
    fwd_solve<<<NB, 512>>>();
    bwd_solve<<<NB, 512>>>();
    predict_kernel<<<N / 32, 256>>>(Xte, Xtr, out);
}